// round 2
// baseline (speedup 1.0000x reference)
#include <cuda_runtime.h>

#define NN 100000
#define NE 3200000
#define NG 4096
#define NRL 5
#define NK (NN*NRL)   // 500000 segments
#define HID 32

// ---------------- scratch (static device globals; no allocation) ----------------
__device__ int   g_src[NE];      // src node per edge (int32)
__device__ int   g_key[NE];      // dst*5+rel per edge
__device__ int   g_cnt[NK];      // per-segment counts
__device__ int   g_off[NK];      // CSR offsets (exclusive scan of cnt)
__device__ int   g_cur[NK];      // scatter cursors
__device__ float g_inv[NK];      // 1/max(cnt,1)
__device__ int   g_ssrc[NE];     // src ids sorted by segment
__device__ int   g_bsum[512];
__device__ int   g_bsumex[512];
__device__ float g_h[(long)NN*128]; // concatenated layer outputs [N,128]

// ---------------- sort / CSR build ----------------
__global__ void k_zero() {
    int i = blockIdx.x * blockDim.x + threadIdx.x;
    if (i < NK) g_cnt[i] = 0;
}

__global__ void k_build(const int* __restrict__ ei, const int* __restrict__ et) {
    int e = blockIdx.x * blockDim.x + threadIdx.x;
    if (e >= NE) return;
    int s = ei[e];
    int d = ei[NE + e];
    int t = et[e];
    int key = d * NRL + t;
    g_src[e] = s;
    g_key[e] = key;
    atomicAdd(&g_cnt[key], 1);
}

__global__ void k_scanA() {
    __shared__ int sh[1024];
    int i = blockIdx.x * 1024 + threadIdx.x;
    int v = (i < NK) ? g_cnt[i] : 0;
    sh[threadIdx.x] = v;
    __syncthreads();
    for (int o = 1; o < 1024; o <<= 1) {
        int t = (threadIdx.x >= o) ? sh[threadIdx.x - o] : 0;
        __syncthreads();
        sh[threadIdx.x] += t;
        __syncthreads();
    }
    if (i < NK) g_off[i] = sh[threadIdx.x] - v;   // exclusive
    if (threadIdx.x == 1023) g_bsum[blockIdx.x] = sh[1023];
}

__global__ void k_scanB(int nb) {
    __shared__ int sh[512];
    int v = (threadIdx.x < nb) ? g_bsum[threadIdx.x] : 0;
    sh[threadIdx.x] = v;
    __syncthreads();
    for (int o = 1; o < 512; o <<= 1) {
        int t = (threadIdx.x >= o) ? sh[threadIdx.x - o] : 0;
        __syncthreads();
        sh[threadIdx.x] += t;
        __syncthreads();
    }
    g_bsumex[threadIdx.x] = sh[threadIdx.x] - v;
}

__global__ void k_scanC() {
    int i = blockIdx.x * blockDim.x + threadIdx.x;
    if (i >= NK) return;
    int o = g_off[i] + g_bsumex[i >> 10];
    g_off[i] = o;
    g_cur[i] = o;
    int c = g_cnt[i];
    g_inv[i] = 1.0f / (float)(c > 0 ? c : 1);
}

__global__ void k_scatter() {
    int e = blockIdx.x * blockDim.x + threadIdx.x;
    if (e >= NE) return;
    int k = g_key[e];
    int p = atomicAdd(&g_cur[k], 1);
    g_ssrc[p] = g_src[e];
}

// ---------------- fused RGCN layer ----------------
// Per node n: aggB[b][i] = sum_r comp[r][b] * inv[n,r] * sum_{e in seg(n,r)} X[src_e][i]
// out[n][o] = tanh( sum_{b,i} aggB[b][i]*basis[b][i][o] + sum_i X[n][i]*root[i][o] + bias[o] )
// Weight matrix in shared: rows 0..4*IN_C-1 = basis ([b*in+i][o] layout),
// rows 4*IN_C..5*IN_C-1 = root.
template<int IN_C>
__global__ void __launch_bounds__(256) k_layer(
    const float* __restrict__ Xin, int xstride, int xoff,
    const float* __restrict__ basis, const float* __restrict__ comp,
    const float* __restrict__ root, const float* __restrict__ bias,
    int yoff)
{
    const int WPB = 8;   // warps per block
    const int NPW = 8;   // nodes per warp
    __shared__ float Wsh[5 * IN_C * 32];
    __shared__ float csh[NRL * 4];
    __shared__ float bsh[32];
    __shared__ float Ash[WPB][5 * IN_C];

    const float* X = Xin ? Xin : g_h;

    int tid = threadIdx.x, w = tid >> 5, lane = tid & 31;
    for (int j = tid; j < 4 * IN_C * 32; j += 256) Wsh[j] = basis[j];
    for (int j = tid; j < IN_C * 32; j += 256) Wsh[4 * IN_C * 32 + j] = root[j];
    if (tid < NRL * 4) csh[tid] = comp[tid];
    if (tid < 32) bsh[tid] = bias[tid];
    __syncthreads();

    int nbase = (blockIdx.x * WPB + w) * NPW;
    for (int ni = 0; ni < NPW; ni++) {
        int n = nbase + ni;
        if (n >= NN) break;   // uniform across warp
        if (lane < IN_C) {
            float a0 = 0.f, a1 = 0.f, a2 = 0.f, a3 = 0.f;
            int e0 = g_off[n * NRL];
            #pragma unroll
            for (int r = 0; r < NRL; r++) {
                int seg = n * NRL + r;
                int e1 = (seg == NK - 1) ? NE : g_off[seg + 1];
                float sum = 0.f;
                for (int e = e0; e < e1; e++) {
                    int s = g_ssrc[e];
                    sum += X[(long)s * xstride + xoff + lane];
                }
                e0 = e1;
                float iv = g_inv[seg] * sum;
                a0 = fmaf(csh[r * 4 + 0], iv, a0);
                a1 = fmaf(csh[r * 4 + 1], iv, a1);
                a2 = fmaf(csh[r * 4 + 2], iv, a2);
                a3 = fmaf(csh[r * 4 + 3], iv, a3);
            }
            Ash[w][0 * IN_C + lane] = a0;
            Ash[w][1 * IN_C + lane] = a1;
            Ash[w][2 * IN_C + lane] = a2;
            Ash[w][3 * IN_C + lane] = a3;
            Ash[w][4 * IN_C + lane] = X[(long)n * xstride + xoff + lane];
        }
        __syncwarp();
        float acc = bsh[lane];
        #pragma unroll 10
        for (int j = 0; j < 5 * IN_C; j++)
            acc = fmaf(Ash[w][j], Wsh[j * 32 + lane], acc);
        g_h[(long)n * 128 + yoff + lane] = tanhf(acc);
        __syncwarp();
    }
}

// ---------------- MLP readout ----------------
__global__ void __launch_bounds__(128) k_mlp(
    const int* __restrict__ uidx, const int* __restrict__ iidx,
    const float* __restrict__ w1, const float* __restrict__ b1,
    const float* __restrict__ w2, const float* __restrict__ b2,
    float* __restrict__ out)
{
    const int GPB = 8;
    __shared__ float gsh[GPB * 256];
    __shared__ float red[128];
    int tid = threadIdx.x;
    int gbase = blockIdx.x * GPB;

    for (int idx = tid; idx < GPB * 256; idx += 128) {
        int gi = idx >> 8, k = idx & 255;
        int g = gbase + gi;
        int n = (k < 128) ? uidx[g] : iidx[g];
        gsh[idx] = g_h[(long)n * 128 + (k & 127)];
    }
    __syncthreads();

    float acc[GPB];
    float bb = b1[tid];
    #pragma unroll
    for (int gi = 0; gi < GPB; gi++) acc[gi] = bb;

    for (int k = 0; k < 256; k++) {
        float wv = w1[k * 128 + tid];
        #pragma unroll
        for (int gi = 0; gi < GPB; gi++)
            acc[gi] = fmaf(gsh[gi * 256 + k], wv, acc[gi]);
    }

    float w2v = w2[tid];
    float b2v = b2[0];
    #pragma unroll
    for (int gi = 0; gi < GPB; gi++) {
        float z = fmaxf(acc[gi], 0.f) * w2v;
        red[tid] = z;
        __syncthreads();
        for (int o = 64; o > 0; o >>= 1) {
            if (tid < o) red[tid] += red[tid + o];
            __syncthreads();
        }
        if (tid == 0) out[gbase + gi] = red[0] + b2v;
        __syncthreads();
    }
}

// ---------------- launcher ----------------
extern "C" void kernel_launch(void* const* d_in, const int* in_sizes, int n_in,
                              void* d_out, int out_size)
{
    const float* x  = (const float*)d_in[0];
    const int*   ei = (const int*)d_in[1];
    const int*   et = (const int*)d_in[2];
    const int*   ui = (const int*)d_in[3];
    const int*   ii = (const int*)d_in[4];
    const float* basis[4] = {(const float*)d_in[5],  (const float*)d_in[9],
                             (const float*)d_in[13], (const float*)d_in[17]};
    const float* comp[4]  = {(const float*)d_in[6],  (const float*)d_in[10],
                             (const float*)d_in[14], (const float*)d_in[18]};
    const float* root[4]  = {(const float*)d_in[7],  (const float*)d_in[11],
                             (const float*)d_in[15], (const float*)d_in[19]};
    const float* bias[4]  = {(const float*)d_in[8],  (const float*)d_in[12],
                             (const float*)d_in[16], (const float*)d_in[20]};
    const float* w1 = (const float*)d_in[21];
    const float* b1 = (const float*)d_in[22];
    const float* w2 = (const float*)d_in[23];
    const float* b2 = (const float*)d_in[24];
    float* out = (float*)d_out;

    // build CSR by (dst,rel) via counting sort
    k_zero<<<(NK + 255) / 256, 256>>>();
    k_build<<<(NE + 255) / 256, 256>>>(ei, et);
    k_scanA<<<(NK + 1023) / 1024, 1024>>>();
    k_scanB<<<1, 512>>>((NK + 1023) / 1024);
    k_scanC<<<(NK + 255) / 256, 256>>>();
    k_scatter<<<(NE + 255) / 256, 256>>>();

    const int nodes_per_block = 64;  // 8 warps * 8 nodes
    int lblocks = (NN + nodes_per_block - 1) / nodes_per_block;

    // layer 0: input x [N,4]
    k_layer<4><<<lblocks, 256>>>(x, 4, 0, basis[0], comp[0], root[0], bias[0], 0);
    // layers 1..3: input = previous layer slice of g_h [N,128]
    k_layer<32><<<lblocks, 256>>>(nullptr, 128, 0,  basis[1], comp[1], root[1], bias[1], 32);
    k_layer<32><<<lblocks, 256>>>(nullptr, 128, 32, basis[2], comp[2], root[2], bias[2], 64);
    k_layer<32><<<lblocks, 256>>>(nullptr, 128, 64, basis[3], comp[3], root[3], bias[3], 96);

    // MLP readout
    k_mlp<<<NG / 8, 128>>>(ui, ii, w1, b1, w2, b2, out);
}

// round 3
// speedup vs baseline: 1.0835x; 1.0835x over previous
#include <cuda_runtime.h>

#define NN 100000
#define NE 3200000
#define NG 4096
#define NRL 5
#define NK (NN*NRL)   // 500000 segments
#define HID 32

// ---------------- scratch (static device globals; no allocation) ----------------
__device__ int   g_cnt[NK];      // per-segment counts
__device__ int   g_off[NK];      // CSR offsets (exclusive scan of cnt)
__device__ int   g_cur[NK];      // scatter cursors
__device__ float g_inv[NK];      // 1/max(cnt,1)
__device__ int   g_ssrc[NE];     // src ids sorted by segment
__device__ int   g_bsum[512];
__device__ int   g_bsumex[512];
__device__ float g_h[(long)NN*128]; // concatenated layer outputs [N,128]

// ---------------- sort / CSR build ----------------
__global__ void k_zero() {
    int i = blockIdx.x * blockDim.x + threadIdx.x;
    if (i < NK) g_cnt[i] = 0;
}

__global__ void k_build(const int* __restrict__ ei, const int* __restrict__ et) {
    int e = blockIdx.x * blockDim.x + threadIdx.x;
    if (e >= NE) return;
    int d = ei[NE + e];
    int t = et[e];
    atomicAdd(&g_cnt[d * NRL + t], 1);
}

__global__ void k_scanA() {
    __shared__ int sh[1024];
    int i = blockIdx.x * 1024 + threadIdx.x;
    int v = (i < NK) ? g_cnt[i] : 0;
    sh[threadIdx.x] = v;
    __syncthreads();
    for (int o = 1; o < 1024; o <<= 1) {
        int t = (threadIdx.x >= o) ? sh[threadIdx.x - o] : 0;
        __syncthreads();
        sh[threadIdx.x] += t;
        __syncthreads();
    }
    if (i < NK) g_off[i] = sh[threadIdx.x] - v;   // exclusive
    if (threadIdx.x == 1023) g_bsum[blockIdx.x] = sh[1023];
}

__global__ void k_scanB(int nb) {
    __shared__ int sh[512];
    int v = (threadIdx.x < nb) ? g_bsum[threadIdx.x] : 0;
    sh[threadIdx.x] = v;
    __syncthreads();
    for (int o = 1; o < 512; o <<= 1) {
        int t = (threadIdx.x >= o) ? sh[threadIdx.x - o] : 0;
        __syncthreads();
        sh[threadIdx.x] += t;
        __syncthreads();
    }
    g_bsumex[threadIdx.x] = sh[threadIdx.x] - v;
}

__global__ void k_scanC() {
    int i = blockIdx.x * blockDim.x + threadIdx.x;
    if (i >= NK) return;
    int o = g_off[i] + g_bsumex[i >> 10];
    g_off[i] = o;
    g_cur[i] = o;
    int c = g_cnt[i];
    g_inv[i] = 1.0f / (float)(c > 0 ? c : 1);
}

__global__ void k_scatter(const int* __restrict__ ei, const int* __restrict__ et) {
    int e = blockIdx.x * blockDim.x + threadIdx.x;
    if (e >= NE) return;
    int s = ei[e];
    int d = ei[NE + e];
    int t = et[e];
    int k = d * NRL + t;
    int p = atomicAdd(&g_cur[k], 1);
    g_ssrc[p] = s;
}

// ---------------- fused RGCN layer (IN_C = 32, lane = feature, edge unroll x4) ----
__global__ void __launch_bounds__(256) k_layer32(
    int xoff,
    const float* __restrict__ basis, const float* __restrict__ comp,
    const float* __restrict__ root, const float* __restrict__ bias,
    int yoff)
{
    const int IN_C = 32;
    const int WPB = 8;   // warps per block
    const int NPW = 8;   // nodes per warp
    __shared__ float Wsh[5 * IN_C * 32];
    __shared__ float csh[NRL * 4];
    __shared__ float bsh[32];
    __shared__ float Ash[WPB][5 * IN_C];

    int tid = threadIdx.x, w = tid >> 5, lane = tid & 31;
    for (int j = tid; j < 4 * IN_C * 32; j += 256) Wsh[j] = basis[j];
    for (int j = tid; j < IN_C * 32; j += 256) Wsh[4 * IN_C * 32 + j] = root[j];
    if (tid < NRL * 4) csh[tid] = comp[tid];
    if (tid < 32) bsh[tid] = bias[tid];
    __syncthreads();

    const float* __restrict__ X = g_h + xoff + lane;   // per-lane feature column

    int nbase = (blockIdx.x * WPB + w) * NPW;
    for (int ni = 0; ni < NPW; ni++) {
        int n = nbase + ni;
        if (n >= NN) break;   // uniform across warp
        float a0 = 0.f, a1 = 0.f, a2 = 0.f, a3 = 0.f;
        int e0 = g_off[n * NRL];
        #pragma unroll
        for (int r = 0; r < NRL; r++) {
            int seg = n * NRL + r;
            int e1 = (seg == NK - 1) ? NE : g_off[seg + 1];
            float s0 = 0.f, s1 = 0.f, s2 = 0.f, s3 = 0.f;
            int e = e0;
            for (; e + 3 < e1; e += 4) {
                int ia = g_ssrc[e + 0];
                int ib = g_ssrc[e + 1];
                int ic = g_ssrc[e + 2];
                int id = g_ssrc[e + 3];
                s0 += X[ia * 128];
                s1 += X[ib * 128];
                s2 += X[ic * 128];
                s3 += X[id * 128];
            }
            for (; e < e1; e++) s0 += X[g_ssrc[e] * 128];
            e0 = e1;
            float iv = g_inv[seg] * ((s0 + s1) + (s2 + s3));
            a0 = fmaf(csh[r * 4 + 0], iv, a0);
            a1 = fmaf(csh[r * 4 + 1], iv, a1);
            a2 = fmaf(csh[r * 4 + 2], iv, a2);
            a3 = fmaf(csh[r * 4 + 3], iv, a3);
        }
        Ash[w][0 * IN_C + lane] = a0;
        Ash[w][1 * IN_C + lane] = a1;
        Ash[w][2 * IN_C + lane] = a2;
        Ash[w][3 * IN_C + lane] = a3;
        Ash[w][4 * IN_C + lane] = X[n * 128];
        __syncwarp();
        float acc = bsh[lane];
        #pragma unroll 10
        for (int j = 0; j < 5 * IN_C; j++)
            acc = fmaf(Ash[w][j], Wsh[j * 32 + lane], acc);
        g_h[(long)n * 128 + yoff + lane] = tanhf(acc);
        __syncwarp();
    }
}

// ---------------- layer 0 (IN_C = 4): 8 edges x 4 features across the warp -----
__global__ void __launch_bounds__(256) k_layer0(
    const float* __restrict__ x,
    const float* __restrict__ basis, const float* __restrict__ comp,
    const float* __restrict__ root, const float* __restrict__ bias)
{
    const int IN_C = 4;
    const int WPB = 8;
    const int NPW = 8;
    __shared__ float Wsh[5 * IN_C * 32];
    __shared__ float csh[NRL * 4];
    __shared__ float bsh[32];
    __shared__ float Ash[WPB][5 * IN_C];

    int tid = threadIdx.x, w = tid >> 5, lane = tid & 31;
    for (int j = tid; j < 4 * IN_C * 32; j += 256) Wsh[j] = basis[j];
    if (tid < IN_C * 32) Wsh[4 * IN_C * 32 + tid] = root[tid];
    if (tid < NRL * 4) csh[tid] = comp[tid];
    if (tid < 32) bsh[tid] = bias[tid];
    __syncthreads();

    int sub  = lane >> 2;   // 0..7 edge subgroup
    int feat = lane & 3;    // 0..3 feature

    int nbase = (blockIdx.x * WPB + w) * NPW;
    for (int ni = 0; ni < NPW; ni++) {
        int n = nbase + ni;
        if (n >= NN) break;   // uniform across warp
        float a0 = 0.f, a1 = 0.f, a2 = 0.f, a3 = 0.f;
        int e0 = g_off[n * NRL];
        #pragma unroll
        for (int r = 0; r < NRL; r++) {
            int seg = n * NRL + r;
            int e1 = (seg == NK - 1) ? NE : g_off[seg + 1];
            float sum = 0.f;
            for (int e = e0 + sub; e < e1; e += 8) {
                int s = g_ssrc[e];
                sum += x[s * 4 + feat];
            }
            e0 = e1;
            // reduce across the 8 edge subgroups (offsets 16, 8, 4)
            sum += __shfl_down_sync(0xffffffffu, sum, 16);
            sum += __shfl_down_sync(0xffffffffu, sum, 8);
            sum += __shfl_down_sync(0xffffffffu, sum, 4);
            if (lane < 4) {
                float iv = g_inv[seg] * sum;
                a0 = fmaf(csh[r * 4 + 0], iv, a0);
                a1 = fmaf(csh[r * 4 + 1], iv, a1);
                a2 = fmaf(csh[r * 4 + 2], iv, a2);
                a3 = fmaf(csh[r * 4 + 3], iv, a3);
            }
        }
        if (lane < 4) {
            Ash[w][0 * IN_C + lane] = a0;
            Ash[w][1 * IN_C + lane] = a1;
            Ash[w][2 * IN_C + lane] = a2;
            Ash[w][3 * IN_C + lane] = a3;
            Ash[w][4 * IN_C + lane] = x[n * 4 + lane];
        }
        __syncwarp();
        float acc = bsh[lane];
        #pragma unroll
        for (int j = 0; j < 5 * IN_C; j++)
            acc = fmaf(Ash[w][j], Wsh[j * 32 + lane], acc);
        g_h[(long)n * 128 + lane] = tanhf(acc);
        __syncwarp();
    }
}

// ---------------- MLP readout ----------------
__global__ void __launch_bounds__(128) k_mlp(
    const int* __restrict__ uidx, const int* __restrict__ iidx,
    const float* __restrict__ w1, const float* __restrict__ b1,
    const float* __restrict__ w2, const float* __restrict__ b2,
    float* __restrict__ out)
{
    const int GPB = 8;
    __shared__ float gsh[GPB * 256];
    __shared__ float red[128];
    int tid = threadIdx.x;
    int gbase = blockIdx.x * GPB;

    for (int idx = tid; idx < GPB * 256; idx += 128) {
        int gi = idx >> 8, k = idx & 255;
        int g = gbase + gi;
        int n = (k < 128) ? uidx[g] : iidx[g];
        gsh[idx] = g_h[(long)n * 128 + (k & 127)];
    }
    __syncthreads();

    float acc[GPB];
    float bb = b1[tid];
    #pragma unroll
    for (int gi = 0; gi < GPB; gi++) acc[gi] = bb;

    for (int k = 0; k < 256; k++) {
        float wv = w1[k * 128 + tid];
        #pragma unroll
        for (int gi = 0; gi < GPB; gi++)
            acc[gi] = fmaf(gsh[gi * 256 + k], wv, acc[gi]);
    }

    float w2v = w2[tid];
    float b2v = b2[0];
    #pragma unroll
    for (int gi = 0; gi < GPB; gi++) {
        float z = fmaxf(acc[gi], 0.f) * w2v;
        red[tid] = z;
        __syncthreads();
        for (int o = 64; o > 0; o >>= 1) {
            if (tid < o) red[tid] += red[tid + o];
            __syncthreads();
        }
        if (tid == 0) out[gbase + gi] = red[0] + b2v;
        __syncthreads();
    }
}

// ---------------- launcher ----------------
extern "C" void kernel_launch(void* const* d_in, const int* in_sizes, int n_in,
                              void* d_out, int out_size)
{
    const float* x  = (const float*)d_in[0];
    const int*   ei = (const int*)d_in[1];
    const int*   et = (const int*)d_in[2];
    const int*   ui = (const int*)d_in[3];
    const int*   ii = (const int*)d_in[4];
    const float* basis[4] = {(const float*)d_in[5],  (const float*)d_in[9],
                             (const float*)d_in[13], (const float*)d_in[17]};
    const float* comp[4]  = {(const float*)d_in[6],  (const float*)d_in[10],
                             (const float*)d_in[14], (const float*)d_in[18]};
    const float* root[4]  = {(const float*)d_in[7],  (const float*)d_in[11],
                             (const float*)d_in[15], (const float*)d_in[19]};
    const float* bias[4]  = {(const float*)d_in[8],  (const float*)d_in[12],
                             (const float*)d_in[16], (const float*)d_in[20]};
    const float* w1 = (const float*)d_in[21];
    const float* b1 = (const float*)d_in[22];
    const float* w2 = (const float*)d_in[23];
    const float* b2 = (const float*)d_in[24];
    float* out = (float*)d_out;

    // build CSR by (dst,rel) via counting sort
    k_zero<<<(NK + 255) / 256, 256>>>();
    k_build<<<(NE + 255) / 256, 256>>>(ei, et);
    k_scanA<<<(NK + 1023) / 1024, 1024>>>();
    k_scanB<<<1, 512>>>((NK + 1023) / 1024);
    k_scanC<<<(NK + 255) / 256, 256>>>();
    k_scatter<<<(NE + 255) / 256, 256>>>(ei, et);

    const int nodes_per_block = 64;  // 8 warps * 8 nodes
    int lblocks = (NN + nodes_per_block - 1) / nodes_per_block;

    // layer 0: input x [N,4]
    k_layer0<<<lblocks, 256>>>(x, basis[0], comp[0], root[0], bias[0]);
    // layers 1..3: input = previous layer slice of g_h [N,128]
    k_layer32<<<lblocks, 256>>>(0,  basis[1], comp[1], root[1], bias[1], 32);
    k_layer32<<<lblocks, 256>>>(32, basis[2], comp[2], root[2], bias[2], 64);
    k_layer32<<<lblocks, 256>>>(64, basis[3], comp[3], root[3], bias[3], 96);

    // MLP readout
    k_mlp<<<NG / 8, 128>>>(ui, ii, w1, b1, w2, b2, out);
}